// round 3
// baseline (speedup 1.0000x reference)
#include <cuda_runtime.h>
#include <math.h>

// Problem constants (fixed: features [512,384] f32, labels [512] i32)
#define NQ 512
#define DIM 384
#define KSPLIT 4
#define KCH (DIM / KSPLIT)   // 96 per split, 3 chunks of 32
#define SCALE 50.0f          // 1/(2*t2), t2 = 0.01  (tanh form of sigmoid)
#define KSEL 6.0f            // K = 5 + 1
#define SAT 9.0f             // |x| >= 9 -> tanh(x) == +/-1 exactly in fp32

// Scratch (no allocations allowed anywhere)
__device__ float g_part[KSPLIT * NQ * NQ];  // partial Gram matrices (4 MB)
__device__ float g_prec[NQ];                // per-query precision sums
__device__ unsigned int g_count = 0;        // ticket counter (reset after use)

__device__ __forceinline__ float fast_tanh(float x) {
    float r;
    asm("tanh.approx.f32 %0, %1;" : "=f"(r) : "f"(x));
    return r;
}

// ---------------------------------------------------------------------------
// Kernel 1: partial Gram.  32(M) x 64(N) tile, K-split across blockIdx.z.
// 512 CTAs total -> 3-4 CTAs/SM, latency hidden. FFMA-bound.
// ---------------------------------------------------------------------------
__global__ __launch_bounds__(256) void gram_kernel(const float* __restrict__ F) {
    __shared__ float As[32][33];   // [row][k]
    __shared__ float Bs[32][68];   // [k][col]

    const int bm = blockIdx.y * 32;
    const int bn = blockIdx.x * 64;
    const int kb = blockIdx.z * KCH;
    const int t  = threadIdx.x;
    const int r0 = (t >> 4) * 2;
    const int c0 = (t & 15) * 4;

    float acc[2][4] = {};

    for (int k0 = kb; k0 < kb + KCH; k0 += 32) {
        #pragma unroll
        for (int i = t; i < 32 * 32; i += 256) {
            int r = i >> 5, c = i & 31;
            As[r][c] = F[(bm + r) * DIM + k0 + c];
        }
        #pragma unroll
        for (int i = t; i < 64 * 32; i += 256) {
            int c = i >> 5, kk = i & 31;
            Bs[kk][c] = F[(bn + c) * DIM + k0 + kk];
        }
        __syncthreads();

        #pragma unroll
        for (int kk = 0; kk < 32; kk++) {
            float a0 = As[r0][kk];
            float a1 = As[r0 + 1][kk];
            float4 b = *reinterpret_cast<const float4*>(&Bs[kk][c0]);
            acc[0][0] = fmaf(a0, b.x, acc[0][0]);
            acc[0][1] = fmaf(a0, b.y, acc[0][1]);
            acc[0][2] = fmaf(a0, b.z, acc[0][2]);
            acc[0][3] = fmaf(a0, b.w, acc[0][3]);
            acc[1][0] = fmaf(a1, b.x, acc[1][0]);
            acc[1][1] = fmaf(a1, b.y, acc[1][1]);
            acc[1][2] = fmaf(a1, b.z, acc[1][2]);
            acc[1][3] = fmaf(a1, b.w, acc[1][3]);
        }
        __syncthreads();
    }

    float* dst = g_part + blockIdx.z * (NQ * NQ);
    #pragma unroll
    for (int i = 0; i < 2; i++) {
        #pragma unroll
        for (int j = 0; j < 4; j++) {
            dst[(bm + r0 + i) * NQ + (bn + c0 + j)] = acc[i][j];
        }
    }
}

// ---------------------------------------------------------------------------
// Kernel 2: rank + precision + fused final reduction.
// One block of 512 threads per query q.
//  - distances from summed Gram partials (diag gives norms)
//  - hybrid bitonic sort of packed (valbits<<32 | index) uint64 keys:
//      j>=32 stages via smem (10 stages), j<=16 stages via shfl (35 stages)
//  - rank = sorted position +/- exact tanh corrections in the |dv|<9 window
//  - last-finishing block reduces g_prec -> scalar loss (deterministic order)
// ---------------------------------------------------------------------------
__global__ __launch_bounds__(NQ) void rank_kernel(const int* __restrict__ labels,
                                                  float* __restrict__ out) {
    __shared__ float sq[NQ];
    __shared__ float sv[NQ];
    __shared__ unsigned long long sk[NQ];
    __shared__ float ws[16];
    __shared__ int isLast;

    const int q = blockIdx.x;
    const int p = threadIdx.x;

    // --- distance a[p] = 50 * d(q, p) from Gram partials ---
    {
        const int dg = p * (NQ + 1);
        float gpp = g_part[dg] + g_part[NQ * NQ + dg]
                  + g_part[2 * NQ * NQ + dg] + g_part[3 * NQ * NQ + dg];
        sq[p] = gpp;
        const int od = q * NQ + p;
        float gqp = g_part[od] + g_part[NQ * NQ + od]
                  + g_part[2 * NQ * NQ + od] + g_part[3 * NQ * NQ + od];
        __syncthreads();
        float d2 = sq[q] + sq[p] - 2.0f * gqp;
        float val = SCALE * sqrtf(fmaxf(d2, 0.0f));
        sk[p] = ((unsigned long long)__float_as_uint(val) << 32) | (unsigned)p;
    }

    // --- hybrid bitonic sort (ascending); keys unique -> deterministic ---
    unsigned long long key = sk[p];
    for (int k = 2; k <= NQ; k <<= 1) {
        // cross-warp stages via smem
        for (int j = k >> 1; j >= 32; j >>= 1) {
            sk[p] = key;
            __syncthreads();
            unsigned long long other = sk[p ^ j];
            __syncthreads();
            const bool wantMin = (((p & j) == 0) == ((p & k) == 0));
            if (wantMin ? (other < key) : (other > key)) key = other;
        }
        // intra-warp stages via shfl (no barriers)
        const int js = ((k >> 1) < 32) ? (k >> 1) : 16;
        for (int j = js; j >= 1; j >>= 1) {
            unsigned long long other = __shfl_xor_sync(0xffffffffu, key, j);
            const bool wantMin = (((p & j) == 0) == ((p & k) == 0));
            if (wantMin ? (other < key) : (other > key)) key = other;
        }
    }

    const float val = __uint_as_float((unsigned)(key >> 32));
    const int gidx  = (int)(key & 0xffffffffu);
    sv[p] = val;
    __syncthreads();

    // --- exact rank: position term + tanh corrections in transition window ---
    float corr = 0.0f;
    for (int j = p - 1; j >= 0; --j) {            // left neighbors: dv > 0
        float dv = val - sv[j];
        if (dv >= SAT) break;
        corr += fast_tanh(dv) - 1.0f;
    }
    for (int j = p + 1; j < NQ; ++j) {            // right neighbors: dv < 0
        float dv = val - sv[j];
        if (dv <= -SAT) break;
        corr += fast_tanh(dv) + 1.0f;
    }
    const float rank = 0.5f * (float)NQ
                     + 0.5f * ((float)(2 * p - (NQ - 1)) + corr);

    float contrib = 0.0f;
    if (labels[q] == labels[gidx]) {
        contrib = 1.0f / (1.0f + __expf(rank - KSEL));   // sigmoid(K - rank)
    }

    // --- per-block reduction (fixed tree, fixed sorted order) ---
    #pragma unroll
    for (int o = 16; o; o >>= 1) contrib += __shfl_xor_sync(0xffffffffu, contrib, o);
    if ((p & 31) == 0) ws[p >> 5] = contrib;
    __syncthreads();
    if (p == 0) {
        float s = 0.0f;
        #pragma unroll
        for (int i = 0; i < 16; i++) s += ws[i];
        g_prec[q] = s;
        __threadfence();
        unsigned int t = atomicAdd(&g_count, 1u);
        isLast = (t == NQ - 1) ? 1 : 0;
    }
    __syncthreads();

    // --- last block performs the deterministic final reduction ---
    if (isLast) {
        float v = g_prec[p];
        #pragma unroll
        for (int o = 16; o; o >>= 1) v += __shfl_xor_sync(0xffffffffu, v, o);
        if ((p & 31) == 0) ws[p >> 5] = v;
        __syncthreads();
        if (p == 0) {
            float s = 0.0f;
            #pragma unroll
            for (int i = 0; i < 16; i++) s += ws[i];
            out[0] = 1.0f - s / (KSEL * (float)NQ);
            g_count = 0;   // reset for next graph replay
        }
    }
}

// ---------------------------------------------------------------------------
extern "C" void kernel_launch(void* const* d_in, const int* in_sizes, int n_in,
                              void* d_out, int out_size) {
    const float* F      = (const float*)d_in[0];
    const int*   labels = (const int*)d_in[1];
    float*       out    = (float*)d_out;

    gram_kernel<<<dim3(NQ / 64, NQ / 32, KSPLIT), 256>>>(F);
    rank_kernel<<<NQ, NQ>>>(labels, out);
}

// round 5
// speedup vs baseline: 1.1449x; 1.1449x over previous
#include <cuda_runtime.h>
#include <math.h>

// Problem constants (fixed: features [512,384] f32, labels [512] i32)
#define NQ 512
#define DIM 384
#define KSPLIT 4
#define KCH (DIM / KSPLIT)   // 96 per split, 3 chunks of 32
#define SCALE 50.0f          // 1/(2*t2), t2 = 0.01  (tanh form of sigmoid)
#define KSEL 6.0f            // K = 5 + 1
#define SAT 9.0f             // |x| >= 9 -> tanh(x) == +/-1 (to fp32 rounding)

// Scratch (no allocations allowed anywhere)
__device__ float g_part[KSPLIT * NQ * NQ];  // partial Gram matrices (4 MB)
__device__ float g_sqp[KSPLIT * NQ];        // partial diagonal (squared norms)
__device__ float g_prec[NQ];                // per-query precision sums
__device__ unsigned int g_count = 0;        // ticket counter (reset after use)

__device__ __forceinline__ float fast_tanh(float x) {
    float r;
    asm("tanh.approx.f32 %0, %1;" : "=f"(r) : "f"(x));
    return r;
}

// ---------------------------------------------------------------------------
// Kernel 1: partial Gram. 32(M) x 64(N) tile, K-split across blockIdx.z.
// Diagonal cells are also written to g_sqp (per-split squared norms).
// ---------------------------------------------------------------------------
__global__ __launch_bounds__(256) void gram_kernel(const float* __restrict__ F) {
    __shared__ float As[32][33];   // [row][k]
    __shared__ float Bs[32][68];   // [k][col]

    const int bm = blockIdx.y * 32;
    const int bn = blockIdx.x * 64;
    const int kb = blockIdx.z * KCH;
    const int t  = threadIdx.x;
    const int r0 = (t >> 4) * 2;
    const int c0 = (t & 15) * 4;

    float acc[2][4] = {};

    for (int k0 = kb; k0 < kb + KCH; k0 += 32) {
        #pragma unroll
        for (int i = t; i < 32 * 32; i += 256) {
            int r = i >> 5, c = i & 31;
            As[r][c] = F[(bm + r) * DIM + k0 + c];
        }
        #pragma unroll
        for (int i = t; i < 64 * 32; i += 256) {
            int c = i >> 5, kk = i & 31;
            Bs[kk][c] = F[(bn + c) * DIM + k0 + kk];
        }
        __syncthreads();

        #pragma unroll
        for (int kk = 0; kk < 32; kk++) {
            float a0 = As[r0][kk];
            float a1 = As[r0 + 1][kk];
            float4 b = *reinterpret_cast<const float4*>(&Bs[kk][c0]);
            acc[0][0] = fmaf(a0, b.x, acc[0][0]);
            acc[0][1] = fmaf(a0, b.y, acc[0][1]);
            acc[0][2] = fmaf(a0, b.z, acc[0][2]);
            acc[0][3] = fmaf(a0, b.w, acc[0][3]);
            acc[1][0] = fmaf(a1, b.x, acc[1][0]);
            acc[1][1] = fmaf(a1, b.y, acc[1][1]);
            acc[1][2] = fmaf(a1, b.z, acc[1][2]);
            acc[1][3] = fmaf(a1, b.w, acc[1][3]);
        }
        __syncthreads();
    }

    float* dst = g_part + blockIdx.z * (NQ * NQ);
    #pragma unroll
    for (int i = 0; i < 2; i++) {
        #pragma unroll
        for (int j = 0; j < 4; j++) {
            const int r = bm + r0 + i;
            const int c = bn + c0 + j;
            dst[r * NQ + c] = acc[i][j];
            if (r == c) g_sqp[blockIdx.z * NQ + r] = acc[i][j];
        }
    }
}

// ---------------------------------------------------------------------------
// Kernel 2: rank + precision + fused final reduction.
// One block of 512 threads per query q. Thread g keeps ORIGINAL gallery slot.
//  - val[g] = 50 * d(q,g) from summed partials (diag via g_sqp side channel)
//  - sort VALUES ONLY (32-bit) with hybrid bitonic: shfl intra-warp,
//    smem cross-warp (10 stages, 20 barriers)
//  - exact rank via binary search (saturated counts) + windowed tanh sum
//  - last-finishing block reduces g_prec -> scalar loss
// ---------------------------------------------------------------------------
__global__ __launch_bounds__(NQ) void rank_kernel(const int* __restrict__ labels,
                                                  float* __restrict__ out) {
    __shared__ float sq[NQ];    // summed squared norms
    __shared__ float sv[NQ];    // sort scratch / sorted values
    __shared__ float ws[16];
    __shared__ int isLast;

    const int q = blockIdx.x;
    const int p = threadIdx.x;

    // --- distance val = 50 * d(q, p); all reads coalesced ---
    sq[p] = g_sqp[p] + g_sqp[NQ + p] + g_sqp[2 * NQ + p] + g_sqp[3 * NQ + p];
    const int od = q * NQ + p;
    float gqp = g_part[od] + g_part[NQ * NQ + od]
              + g_part[2 * NQ * NQ + od] + g_part[3 * NQ * NQ + od];
    __syncthreads();
    const float sqq = sq[q];
    const float val = SCALE * sqrtf(fmaxf(sqq + sq[p] - 2.0f * gqp, 0.0f));

    // --- bitonic sort of values (ascending); thread p holds slot p ---
    float key = val;
    for (int k = 2; k <= NQ; k <<= 1) {
        for (int j = k >> 1; j >= 32; j >>= 1) {          // cross-warp via smem
            sv[p] = key;
            __syncthreads();
            float other = sv[p ^ j];
            __syncthreads();
            const bool wantMin = (((p & j) == 0) == ((p & k) == 0));
            if (wantMin ? (other < key) : (other > key)) key = other;
        }
        const int j0 = ((k >> 1) < 32) ? (k >> 1) : 16;   // intra-warp via shfl
        for (int j = j0; j >= 1; j >>= 1) {
            float other = __shfl_xor_sync(0xffffffffu, key, j);
            const bool wantMin = (((p & j) == 0) == ((p & k) == 0));
            if (wantMin ? (other < key) : (other > key)) key = other;
        }
    }
    sv[p] = key;
    __syncthreads();

    // --- exact rank: saturated counts via binary search + window sum ---
    // wlo = first idx with sv[idx] > val - SAT  (below: tanh == +1)
    const float loB = val - SAT;
    int lo = 0, hi = NQ;
    #pragma unroll
    for (int it = 0; it < 9; it++) {
        int m = (lo + hi) >> 1;
        if (sv[m] <= loB) lo = m + 1; else hi = m;
    }
    const int wlo = lo;
    // whi = first idx with sv[idx] >= val + SAT (from there: tanh == -1)
    const float hiB = val + SAT;
    lo = 0; hi = NQ;
    #pragma unroll
    for (int it = 0; it < 9; it++) {
        int m = (lo + hi) >> 1;
        if (sv[m] < hiB) lo = m + 1; else hi = m;
    }
    const int whi = lo;

    float corr = (float)(wlo - (NQ - whi));
    for (int j = wlo; j < whi; j++) {
        corr += fast_tanh(val - sv[j]);
    }
    const float rank = 0.5f * (float)NQ + 0.5f * corr;

    float contrib = 0.0f;
    if (labels[q] == labels[p]) {
        contrib = 1.0f / (1.0f + __expf(rank - KSEL));   // sigmoid(K - rank)
    }

    // --- per-block reduction (fixed tree, original g order) ---
    #pragma unroll
    for (int o = 16; o; o >>= 1) contrib += __shfl_xor_sync(0xffffffffu, contrib, o);
    if ((p & 31) == 0) ws[p >> 5] = contrib;
    __syncthreads();
    if (p == 0) {
        float s = 0.0f;
        #pragma unroll
        for (int i = 0; i < 16; i++) s += ws[i];
        g_prec[q] = s;
        __threadfence();
        unsigned int t = atomicAdd(&g_count, 1u);
        isLast = (t == NQ - 1) ? 1 : 0;
    }
    __syncthreads();

    // --- last block: deterministic final reduction ---
    if (isLast) {
        __threadfence();
        float v = g_prec[p];
        #pragma unroll
        for (int o = 16; o; o >>= 1) v += __shfl_xor_sync(0xffffffffu, v, o);
        if ((p & 31) == 0) ws[p >> 5] = v;
        __syncthreads();
        if (p == 0) {
            float s = 0.0f;
            #pragma unroll
            for (int i = 0; i < 16; i++) s += ws[i];
            out[0] = 1.0f - s / (KSEL * (float)NQ);
            g_count = 0;   // reset for next graph replay
        }
    }
}

// ---------------------------------------------------------------------------
extern "C" void kernel_launch(void* const* d_in, const int* in_sizes, int n_in,
                              void* d_out, int out_size) {
    const float* F      = (const float*)d_in[0];
    const int*   labels = (const int*)d_in[1];
    float*       out    = (float*)d_out;

    gram_kernel<<<dim3(NQ / 64, NQ / 32, KSPLIT), 256>>>(F);
    rank_kernel<<<NQ, NQ>>>(labels, out);
}

// round 8
// speedup vs baseline: 1.1496x; 1.0041x over previous
#include <cuda_runtime.h>
#include <math.h>

// Problem constants (fixed: features [512,384] f32, labels [512] i32)
#define NQ 512
#define DIM 384
#define KSPLIT 4
#define KCH (DIM / KSPLIT)   // 96 per split, 3 chunks of 32
#define SCALE 50.0f          // 1/(2*t2), t2 = 0.01  (tanh form of sigmoid)
#define KSEL 6.0f            // K = 5 + 1
#define SAT 9.0f             // |x| >= 9 -> tanh(x) == +/-1 (to fp32 rounding)

// Scratch (no allocations allowed anywhere)
__device__ float g_part[KSPLIT * NQ * NQ];  // partial Gram matrices (4 MB)
__device__ float g_sqp[KSPLIT * NQ];        // partial diagonal (squared norms)
__device__ float g_prec[NQ];                // per-query precision sums
__device__ unsigned int g_count = 0;        // ticket counter (reset after use)

__device__ __forceinline__ float fast_tanh(float x) {
    float r;
    asm("tanh.approx.f32 %0, %1;" : "=f"(r) : "f"(x));
    return r;
}

// ---------------------------------------------------------------------------
// Kernel 1: partial Gram (VERBATIM known-good R5 version).
// 32(M) x 64(N) tile, 2x4 microtile, K-split across blockIdx.z.
// ---------------------------------------------------------------------------
__global__ __launch_bounds__(256) void gram_kernel(const float* __restrict__ F) {
    __shared__ float As[32][33];   // [row][k]
    __shared__ float Bs[32][68];   // [k][col]

    const int bm = blockIdx.y * 32;
    const int bn = blockIdx.x * 64;
    const int kb = blockIdx.z * KCH;
    const int t  = threadIdx.x;
    const int r0 = (t >> 4) * 2;
    const int c0 = (t & 15) * 4;

    float acc[2][4] = {};

    for (int k0 = kb; k0 < kb + KCH; k0 += 32) {
        #pragma unroll
        for (int i = t; i < 32 * 32; i += 256) {
            int r = i >> 5, c = i & 31;
            As[r][c] = F[(bm + r) * DIM + k0 + c];
        }
        #pragma unroll
        for (int i = t; i < 64 * 32; i += 256) {
            int c = i >> 5, kk = i & 31;
            Bs[kk][c] = F[(bn + c) * DIM + k0 + kk];
        }
        __syncthreads();

        #pragma unroll
        for (int kk = 0; kk < 32; kk++) {
            float a0 = As[r0][kk];
            float a1 = As[r0 + 1][kk];
            float4 b = *reinterpret_cast<const float4*>(&Bs[kk][c0]);
            acc[0][0] = fmaf(a0, b.x, acc[0][0]);
            acc[0][1] = fmaf(a0, b.y, acc[0][1]);
            acc[0][2] = fmaf(a0, b.z, acc[0][2]);
            acc[0][3] = fmaf(a0, b.w, acc[0][3]);
            acc[1][0] = fmaf(a1, b.x, acc[1][0]);
            acc[1][1] = fmaf(a1, b.y, acc[1][1]);
            acc[1][2] = fmaf(a1, b.z, acc[1][2]);
            acc[1][3] = fmaf(a1, b.w, acc[1][3]);
        }
        __syncthreads();
    }

    float* dst = g_part + blockIdx.z * (NQ * NQ);
    #pragma unroll
    for (int i = 0; i < 2; i++) {
        #pragma unroll
        for (int j = 0; j < 4; j++) {
            const int r = bm + r0 + i;
            const int c = bn + c0 + j;
            dst[r * NQ + c] = acc[i][j];
            if (r == c) g_sqp[blockIdx.z * NQ + r] = acc[i][j];
        }
    }
}

// ---------------------------------------------------------------------------
// Kernel 2: rank + precision + fused final reduction.
// One block of 512 threads per query q.
//  - val = 50 * d(q,p) from summed partials (coalesced)
//  - KEY-VALUE hybrid bitonic sort: key = float value (single FSETP compare),
//    payload = original gallery index (follows the exchange decision).
//    Ties -> no exchange -> still a bijection; tie order irrelevant (tanh(0)=0).
//  - rank at sorted slot p: exact integer position term + small (tanh -/+ 1)
//    corrections via warp-uniform symmetric-offset window (conflict-free LDS,
//    no divergence).
//  - mask uses labels[gidx] (the PERMUTED index) -- the R6/R7 bug fix.
//  - last-finishing block reduces g_prec -> scalar loss.
// ---------------------------------------------------------------------------
__global__ __launch_bounds__(NQ) void rank_kernel(const int* __restrict__ labels,
                                                  float* __restrict__ out) {
    __shared__ float sq[NQ];         // summed squared norms
    __shared__ float sv[NQ];         // sort scratch / sorted values
    __shared__ unsigned sidx[NQ];    // sort scratch for payload
    __shared__ float ws[16];
    __shared__ int isLast;

    const int q = blockIdx.x;
    const int p = threadIdx.x;

    // --- distance val0 = 50 * d(q, p); all reads coalesced ---
    sq[p] = g_sqp[p] + g_sqp[NQ + p] + g_sqp[2 * NQ + p] + g_sqp[3 * NQ + p];
    const int od = q * NQ + p;
    float gqp = g_part[od] + g_part[NQ * NQ + od]
              + g_part[2 * NQ * NQ + od] + g_part[3 * NQ * NQ + od];
    __syncthreads();
    const float val0 = SCALE * sqrtf(fmaxf(sq[q] + sq[p] - 2.0f * gqp, 0.0f));

    // --- key-value bitonic sort (ascending by value) ---
    float key = val0;
    unsigned idx = (unsigned)p;
    for (int k = 2; k <= NQ; k <<= 1) {
        for (int j = k >> 1; j >= 32; j >>= 1) {          // cross-warp via smem
            sv[p] = key;
            sidx[p] = idx;
            __syncthreads();
            float ov = sv[p ^ j];
            unsigned oi = sidx[p ^ j];
            __syncthreads();
            const bool wantMin = (((p & j) == 0) == ((p & k) == 0));
            const bool take = wantMin ? (ov < key) : (ov > key);
            if (take) { key = ov; idx = oi; }
        }
        const int j0 = ((k >> 1) < 32) ? (k >> 1) : 16;   // intra-warp via shfl
        for (int j = j0; j >= 1; j >>= 1) {
            float ov = __shfl_xor_sync(0xffffffffu, key, j);
            unsigned oi = __shfl_xor_sync(0xffffffffu, idx, j);
            const bool wantMin = (((p & j) == 0) == ((p & k) == 0));
            const bool take = wantMin ? (ov < key) : (ov > key);
            if (take) { key = ov; idx = oi; }
        }
    }
    sv[p] = key;
    __syncthreads();
    const float val = key;          // value at sorted slot p
    const int gidx  = (int)idx;     // original gallery index at sorted slot p

    // --- rank: exact position term + small tanh corrections.
    // Warp-uniform symmetric-offset loop: conflict-free LDS, no divergence.
    float corr = 0.0f;
    for (int o = 1; o < NQ; o++) {
        const int jl = p - o;
        const int jr = p + o;
        const float dvL = (jl >= 0) ? (val - sv[jl]) : SAT;    // >= 0
        const float dvR = (jr < NQ) ? (val - sv[jr]) : -SAT;   // <= 0
        const bool uL = dvL < SAT;
        const bool uR = dvR > -SAT;
        if (uL) corr += fast_tanh(dvL) - 1.0f;   // small
        if (uR) corr += fast_tanh(dvR) + 1.0f;   // small
        if (!__any_sync(0xffffffffu, uL || uR)) break;
    }
    const float rank = 0.5f * (float)NQ
                     + 0.5f * ((float)(2 * p - (NQ - 1)) + corr);

    float contrib = 0.0f;
    if (labels[q] == labels[gidx]) {
        contrib = 1.0f / (1.0f + __expf(rank - KSEL));   // sigmoid(K - rank)
    }

    // --- per-block reduction (fixed tree, sorted order -> deterministic) ---
    #pragma unroll
    for (int o = 16; o; o >>= 1) contrib += __shfl_xor_sync(0xffffffffu, contrib, o);
    if ((p & 31) == 0) ws[p >> 5] = contrib;
    __syncthreads();
    if (p == 0) {
        float s = 0.0f;
        #pragma unroll
        for (int i = 0; i < 16; i++) s += ws[i];
        g_prec[q] = s;
        __threadfence();
        unsigned int t = atomicAdd(&g_count, 1u);
        isLast = (t == NQ - 1) ? 1 : 0;
    }
    __syncthreads();

    // --- last block: deterministic final reduction ---
    if (isLast) {
        __threadfence();
        float v = g_prec[p];
        #pragma unroll
        for (int o = 16; o; o >>= 1) v += __shfl_xor_sync(0xffffffffu, v, o);
        if ((p & 31) == 0) ws[p >> 5] = v;
        __syncthreads();
        if (p == 0) {
            float s = 0.0f;
            #pragma unroll
            for (int i = 0; i < 16; i++) s += ws[i];
            out[0] = 1.0f - s / (KSEL * (float)NQ);
            g_count = 0;   // reset for next graph replay
        }
    }
}

// ---------------------------------------------------------------------------
extern "C" void kernel_launch(void* const* d_in, const int* in_sizes, int n_in,
                              void* d_out, int out_size) {
    const float* F      = (const float*)d_in[0];
    const int*   labels = (const int*)d_in[1];
    float*       out    = (float*)d_out;

    gram_kernel<<<dim3(NQ / 64, NQ / 32, KSPLIT), 256>>>(F);
    rank_kernel<<<NQ, NQ>>>(labels, out);
}

// round 9
// speedup vs baseline: 1.2773x; 1.1111x over previous
#include <cuda_runtime.h>
#include <math.h>

// Problem constants (fixed: features [512,384] f32, labels [512] i32)
#define NQ 512
#define DIM 384
#define KSPLIT 4
#define KCH (DIM / KSPLIT)   // 96 per split, 3 chunks of 32
#define SCALE 50.0f          // 1/(2*t2), t2 = 0.01  (tanh form of sigmoid)
#define KSEL 6.0f            // K = 5 + 1
#define SAT 9.0f             // |x| >= 9 -> tanh(x) == +/-1 (to fp32 rounding)
#define QMUL 2048.0f         // key quantizer: val*2048 < 2^23 for val < 4096

// Scratch (no allocations allowed anywhere)
__device__ float g_part[KSPLIT * NQ * NQ];  // partial Gram matrices (4 MB)
__device__ float g_sqp[KSPLIT * NQ];        // partial diagonal (squared norms)
__device__ float g_prec[NQ];                // per-query precision sums
__device__ unsigned int g_count = 0;        // ticket counter (reset after use)

__device__ __forceinline__ float fast_tanh(float x) {
    float r;
    asm("tanh.approx.f32 %0, %1;" : "=f"(r) : "f"(x));
    return r;
}

// ---------------------------------------------------------------------------
// Kernel 1: partial Gram (VERBATIM known-good R5 version).
// 32(M) x 64(N) tile, 2x4 microtile, K-split across blockIdx.z.
// ---------------------------------------------------------------------------
__global__ __launch_bounds__(256) void gram_kernel(const float* __restrict__ F) {
    __shared__ float As[32][33];   // [row][k]
    __shared__ float Bs[32][68];   // [k][col]

    const int bm = blockIdx.y * 32;
    const int bn = blockIdx.x * 64;
    const int kb = blockIdx.z * KCH;
    const int t  = threadIdx.x;
    const int r0 = (t >> 4) * 2;
    const int c0 = (t & 15) * 4;

    float acc[2][4] = {};

    for (int k0 = kb; k0 < kb + KCH; k0 += 32) {
        #pragma unroll
        for (int i = t; i < 32 * 32; i += 256) {
            int r = i >> 5, c = i & 31;
            As[r][c] = F[(bm + r) * DIM + k0 + c];
        }
        #pragma unroll
        for (int i = t; i < 64 * 32; i += 256) {
            int c = i >> 5, kk = i & 31;
            Bs[kk][c] = F[(bn + c) * DIM + k0 + kk];
        }
        __syncthreads();

        #pragma unroll
        for (int kk = 0; kk < 32; kk++) {
            float a0 = As[r0][kk];
            float a1 = As[r0 + 1][kk];
            float4 b = *reinterpret_cast<const float4*>(&Bs[kk][c0]);
            acc[0][0] = fmaf(a0, b.x, acc[0][0]);
            acc[0][1] = fmaf(a0, b.y, acc[0][1]);
            acc[0][2] = fmaf(a0, b.z, acc[0][2]);
            acc[0][3] = fmaf(a0, b.w, acc[0][3]);
            acc[1][0] = fmaf(a1, b.x, acc[1][0]);
            acc[1][1] = fmaf(a1, b.y, acc[1][1]);
            acc[1][2] = fmaf(a1, b.z, acc[1][2]);
            acc[1][3] = fmaf(a1, b.w, acc[1][3]);
        }
        __syncthreads();
    }

    float* dst = g_part + blockIdx.z * (NQ * NQ);
    #pragma unroll
    for (int i = 0; i < 2; i++) {
        #pragma unroll
        for (int j = 0; j < 4; j++) {
            const int r = bm + r0 + i;
            const int c = bn + c0 + j;
            dst[r * NQ + c] = acc[i][j];
            if (r == c) g_sqp[blockIdx.z * NQ + r] = acc[i][j];
        }
    }
}

// ---------------------------------------------------------------------------
// Kernel 2: rank + precision + fused final reduction.
// One block of 512 threads per query q.
//  - SINGLE-WORD sort keys: (quantized value << 9) | original index.
//    Unique -> deterministic; exchanges are SHFL + UMIN/UMAX (no payload).
//  - Exact values recovered post-sort via va[idx]; the rank identity
//    (base +/-1) + (tanh -/+ 1) = tanh(dv) holds under any permutation, so
//    quantization-order jitter introduces ZERO error (ties are deep inside
//    the +/-9 window; tanh(9 - 5e-4) rounds to 1.0f).
//  - warp-uniform symmetric-offset window loop on exact sorted values.
//  - mask via labels staged in smem, indexed by recovered original index.
//  - last-finishing block reduces g_prec -> scalar loss.
// ---------------------------------------------------------------------------
__global__ __launch_bounds__(NQ) void rank_kernel(const int* __restrict__ labels,
                                                  float* __restrict__ out) {
    __shared__ float sq[NQ];         // summed squared norms
    __shared__ float va[NQ];         // exact value by ORIGINAL index
    __shared__ unsigned su[NQ];      // sort scratch (packed keys)
    __shared__ float sve[NQ];        // exact values in sorted order
    __shared__ int   sl[NQ];         // labels staged in smem
    __shared__ float ws[16];
    __shared__ int isLast;

    const int q = blockIdx.x;
    const int p = threadIdx.x;

    // --- distance val0 = 50 * d(q, p); all reads coalesced ---
    sq[p] = g_sqp[p] + g_sqp[NQ + p] + g_sqp[2 * NQ + p] + g_sqp[3 * NQ + p];
    sl[p] = labels[p];
    const int od = q * NQ + p;
    float gqp = g_part[od] + g_part[NQ * NQ + od]
              + g_part[2 * NQ * NQ + od] + g_part[3 * NQ * NQ + od];
    __syncthreads();
    const float val0 = SCALE * sqrtf(fmaxf(sq[q] + sq[p] - 2.0f * gqp, 0.0f));
    va[p] = val0;

    // --- packed key: quantized value (23b) | original index (9b) ---
    unsigned key = ((unsigned)(val0 * QMUL) << 9) | (unsigned)p;

    // --- bitonic sort of packed keys (ascending) ---
    for (int k = 2; k <= NQ; k <<= 1) {
        const bool asc = ((p & k) == 0);
        for (int j = k >> 1; j >= 32; j >>= 1) {          // cross-warp via smem
            su[p] = key;
            __syncthreads();
            unsigned ov = su[p ^ j];
            __syncthreads();
            const bool wantMin = (((p & j) == 0) == asc);
            key = wantMin ? umin(key, ov) : umax(key, ov);
        }
        const int j0 = ((k >> 1) < 32) ? (k >> 1) : 16;   // intra-warp via shfl
        for (int j = j0; j >= 1; j >>= 1) {
            unsigned ov = __shfl_xor_sync(0xffffffffu, key, j);
            const bool wantMin = (((p & j) == 0) == asc);
            key = wantMin ? umin(key, ov) : umax(key, ov);
        }
    }

    // --- recover exact value + original index at sorted slot p ---
    const int gidx = (int)(key & 511u);
    const float val = va[gidx];          // one scattered LDS per thread
    sve[p] = val;
    __syncthreads();

    // --- rank: exact position term + small tanh corrections ---
    float corr = 0.0f;
    for (int o = 1; o < NQ; o++) {
        const int jl = p - o;
        const int jr = p + o;
        const float dvL = (jl >= 0) ? (val - sve[jl]) : SAT;    // ~>= 0
        const float dvR = (jr < NQ) ? (val - sve[jr]) : -SAT;   // ~<= 0
        const bool uL = dvL < SAT;
        const bool uR = dvR > -SAT;
        if (uL) corr += fast_tanh(dvL) - 1.0f;   // small
        if (uR) corr += fast_tanh(dvR) + 1.0f;   // small
        if (!__any_sync(0xffffffffu, uL || uR)) break;
    }
    const float rank = 0.5f * (float)NQ
                     + 0.5f * ((float)(2 * p - (NQ - 1)) + corr);

    float contrib = 0.0f;
    if (sl[q] == sl[gidx]) {
        contrib = 1.0f / (1.0f + __expf(rank - KSEL));   // sigmoid(K - rank)
    }

    // --- per-block reduction (fixed tree, sorted order -> deterministic) ---
    #pragma unroll
    for (int o = 16; o; o >>= 1) contrib += __shfl_xor_sync(0xffffffffu, contrib, o);
    if ((p & 31) == 0) ws[p >> 5] = contrib;
    __syncthreads();
    if (p == 0) {
        float s = 0.0f;
        #pragma unroll
        for (int i = 0; i < 16; i++) s += ws[i];
        g_prec[q] = s;
        __threadfence();
        unsigned int t = atomicAdd(&g_count, 1u);
        isLast = (t == NQ - 1) ? 1 : 0;
    }
    __syncthreads();

    // --- last block: deterministic final reduction ---
    if (isLast) {
        __threadfence();
        float v = g_prec[p];
        #pragma unroll
        for (int o = 16; o; o >>= 1) v += __shfl_xor_sync(0xffffffffu, v, o);
        if ((p & 31) == 0) ws[p >> 5] = v;
        __syncthreads();
        if (p == 0) {
            float s = 0.0f;
            #pragma unroll
            for (int i = 0; i < 16; i++) s += ws[i];
            out[0] = 1.0f - s / (KSEL * (float)NQ);
            g_count = 0;   // reset for next graph replay
        }
    }
}

// ---------------------------------------------------------------------------
extern "C" void kernel_launch(void* const* d_in, const int* in_sizes, int n_in,
                              void* d_out, int out_size) {
    const float* F      = (const float*)d_in[0];
    const int*   labels = (const int*)d_in[1];
    float*       out    = (float*)d_out;

    gram_kernel<<<dim3(NQ / 64, NQ / 32, KSPLIT), 256>>>(F);
    rank_kernel<<<NQ, NQ>>>(labels, out);
}

// round 10
// speedup vs baseline: 1.4900x; 1.1665x over previous
#include <cuda_runtime.h>
#include <math.h>

// Problem constants (fixed: features [512,384] f32, labels [512] i32)
#define NQ 512
#define DIM 384
#define KSPLIT 4
#define KCH (DIM / KSPLIT)   // 96 per split, 3 chunks of 32
#define SCALE 50.0f          // 1/(2*t2), t2 = 0.01  (tanh form of sigmoid)
#define KSEL 6.0f            // K = 5 + 1
#define SAT 5.0f             // truncation cut: |tanh|-1 < 9.1e-5 beyond; net
                             // rank error ~2e-4 with L/R cancellation -> loss
                             // rel err ~1e-5, far under the 1e-3 threshold
#define QMUL 2048.0f         // key quantizer: val*2048 < 2^23 for val < 4096

// Scratch (no allocations allowed anywhere)
__device__ float g_part[KSPLIT * NQ * NQ];  // partial Gram matrices (4 MB)
__device__ float g_sqp[KSPLIT * NQ];        // partial diagonal (squared norms)
__device__ float g_prec[NQ];                // per-query precision sums
__device__ unsigned int g_count = 0;        // ticket counter (reset after use)

__device__ __forceinline__ float fast_tanh(float x) {
    float r;
    asm("tanh.approx.f32 %0, %1;" : "=f"(r) : "f"(x));
    return r;
}

// ---------------------------------------------------------------------------
// Kernel 1: partial Gram (VERBATIM known-good R5 version).
// 32(M) x 64(N) tile, 2x4 microtile, K-split across blockIdx.z.
// ---------------------------------------------------------------------------
__global__ __launch_bounds__(256) void gram_kernel(const float* __restrict__ F) {
    __shared__ float As[32][33];   // [row][k]
    __shared__ float Bs[32][68];   // [k][col]

    const int bm = blockIdx.y * 32;
    const int bn = blockIdx.x * 64;
    const int kb = blockIdx.z * KCH;
    const int t  = threadIdx.x;
    const int r0 = (t >> 4) * 2;
    const int c0 = (t & 15) * 4;

    float acc[2][4] = {};

    for (int k0 = kb; k0 < kb + KCH; k0 += 32) {
        #pragma unroll
        for (int i = t; i < 32 * 32; i += 256) {
            int r = i >> 5, c = i & 31;
            As[r][c] = F[(bm + r) * DIM + k0 + c];
        }
        #pragma unroll
        for (int i = t; i < 64 * 32; i += 256) {
            int c = i >> 5, kk = i & 31;
            Bs[kk][c] = F[(bn + c) * DIM + k0 + kk];
        }
        __syncthreads();

        #pragma unroll
        for (int kk = 0; kk < 32; kk++) {
            float a0 = As[r0][kk];
            float a1 = As[r0 + 1][kk];
            float4 b = *reinterpret_cast<const float4*>(&Bs[kk][c0]);
            acc[0][0] = fmaf(a0, b.x, acc[0][0]);
            acc[0][1] = fmaf(a0, b.y, acc[0][1]);
            acc[0][2] = fmaf(a0, b.z, acc[0][2]);
            acc[0][3] = fmaf(a0, b.w, acc[0][3]);
            acc[1][0] = fmaf(a1, b.x, acc[1][0]);
            acc[1][1] = fmaf(a1, b.y, acc[1][1]);
            acc[1][2] = fmaf(a1, b.z, acc[1][2]);
            acc[1][3] = fmaf(a1, b.w, acc[1][3]);
        }
        __syncthreads();
    }

    float* dst = g_part + blockIdx.z * (NQ * NQ);
    #pragma unroll
    for (int i = 0; i < 2; i++) {
        #pragma unroll
        for (int j = 0; j < 4; j++) {
            const int r = bm + r0 + i;
            const int c = bn + c0 + j;
            dst[r * NQ + c] = acc[i][j];
            if (r == c) g_sqp[blockIdx.z * NQ + r] = acc[i][j];
        }
    }
}

// ---------------------------------------------------------------------------
// Kernel 2: rank + precision + fused final reduction.
// One block of 512 threads per query q.
//  - packed-key bitonic sort (SHFL+UMIN/UMAX), unchanged from R9
//  - sorted values stored into a SENTINEL-PADDED array (+/-1e9, NQ each side)
//    -> no bounds predicates in the window loop
//  - window loop UNROLLED x4 with one warp vote per group; SAT=5
//  - last-finishing block reduces g_prec -> scalar loss
// ---------------------------------------------------------------------------
__global__ __launch_bounds__(NQ) void rank_kernel(const int* __restrict__ labels,
                                                  float* __restrict__ out) {
    __shared__ float sq[NQ];          // summed squared norms
    __shared__ float va[NQ];          // exact value by ORIGINAL index
    __shared__ unsigned su[NQ];       // sort scratch (packed keys)
    __shared__ float sve[3 * NQ];     // [0,NQ): -1e9 | [NQ,2NQ): sorted | [2NQ,3NQ): +1e9
    __shared__ int   sl[NQ];          // labels staged in smem
    __shared__ float ws[16];
    __shared__ int isLast;

    const int q = blockIdx.x;
    const int p = threadIdx.x;

    // --- distance val0 = 50 * d(q, p); all reads coalesced ---
    sq[p] = g_sqp[p] + g_sqp[NQ + p] + g_sqp[2 * NQ + p] + g_sqp[3 * NQ + p];
    sl[p] = labels[p];
    sve[p] = -1.0e9f;                 // left sentinel pad
    sve[2 * NQ + p] = 1.0e9f;         // right sentinel pad
    const int od = q * NQ + p;
    float gqp = g_part[od] + g_part[NQ * NQ + od]
              + g_part[2 * NQ * NQ + od] + g_part[3 * NQ * NQ + od];
    __syncthreads();
    const float val0 = SCALE * sqrtf(fmaxf(sq[q] + sq[p] - 2.0f * gqp, 0.0f));
    va[p] = val0;

    // --- packed key: quantized value (23b) | original index (9b) ---
    unsigned key = ((unsigned)(val0 * QMUL) << 9) | (unsigned)p;

    // --- bitonic sort of packed keys (ascending) ---
    for (int k = 2; k <= NQ; k <<= 1) {
        const bool asc = ((p & k) == 0);
        for (int j = k >> 1; j >= 32; j >>= 1) {          // cross-warp via smem
            su[p] = key;
            __syncthreads();
            unsigned ov = su[p ^ j];
            __syncthreads();
            const bool wantMin = (((p & j) == 0) == asc);
            key = wantMin ? umin(key, ov) : umax(key, ov);
        }
        const int j0 = ((k >> 1) < 32) ? (k >> 1) : 16;   // intra-warp via shfl
        for (int j = j0; j >= 1; j >>= 1) {
            unsigned ov = __shfl_xor_sync(0xffffffffu, key, j);
            const bool wantMin = (((p & j) == 0) == asc);
            key = wantMin ? umin(key, ov) : umax(key, ov);
        }
    }

    // --- recover exact value + original index at sorted slot p ---
    const int gidx = (int)(key & 511u);
    const float val = va[gidx];          // one scattered LDS per thread
    sve[NQ + p] = val;
    __syncthreads();

    // --- rank: exact position term + small tanh corrections.
    // Unrolled x4, sentinel-padded (no bounds checks), one vote per group.
    const float* sc = sve + NQ + p;      // sc[-o] left, sc[o] right
    float corr = 0.0f;
    for (int o = 1; o < NQ; o += 4) {
        bool live = false;
        #pragma unroll
        for (int u = 0; u < 4; u++) {
            const float dvL = val - sc[-(o + u)];   // ~>= 0, grows with o
            const float dvR = val - sc[o + u];      // ~<= 0, falls with o
            const bool uL = dvL < SAT;
            const bool uR = dvR > -SAT;
            if (uL) corr += fast_tanh(dvL) - 1.0f;  // small
            if (uR) corr += fast_tanh(dvR) + 1.0f;  // small
            live |= (uL || uR);
        }
        if (!__any_sync(0xffffffffu, live)) break;
    }
    const float rank = 0.5f * (float)NQ
                     + 0.5f * ((float)(2 * p - (NQ - 1)) + corr);

    float contrib = 0.0f;
    if (sl[q] == sl[gidx]) {
        contrib = 1.0f / (1.0f + __expf(rank - KSEL));   // sigmoid(K - rank)
    }

    // --- per-block reduction (fixed tree, sorted order -> deterministic) ---
    #pragma unroll
    for (int o = 16; o; o >>= 1) contrib += __shfl_xor_sync(0xffffffffu, contrib, o);
    if ((p & 31) == 0) ws[p >> 5] = contrib;
    __syncthreads();
    if (p == 0) {
        float s = 0.0f;
        #pragma unroll
        for (int i = 0; i < 16; i++) s += ws[i];
        g_prec[q] = s;
        __threadfence();
        unsigned int t = atomicAdd(&g_count, 1u);
        isLast = (t == NQ - 1) ? 1 : 0;
    }
    __syncthreads();

    // --- last block: deterministic final reduction ---
    if (isLast) {
        __threadfence();
        float v = g_prec[p];
        #pragma unroll
        for (int o = 16; o; o >>= 1) v += __shfl_xor_sync(0xffffffffu, v, o);
        if ((p & 31) == 0) ws[p >> 5] = v;
        __syncthreads();
        if (p == 0) {
            float s = 0.0f;
            #pragma unroll
            for (int i = 0; i < 16; i++) s += ws[i];
            out[0] = 1.0f - s / (KSEL * (float)NQ);
            g_count = 0;   // reset for next graph replay
        }
    }
}

// ---------------------------------------------------------------------------
extern "C" void kernel_launch(void* const* d_in, const int* in_sizes, int n_in,
                              void* d_out, int out_size) {
    const float* F      = (const float*)d_in[0];
    const int*   labels = (const int*)d_in[1];
    float*       out    = (float*)d_out;

    gram_kernel<<<dim3(NQ / 64, NQ / 32, KSPLIT), 256>>>(F);
    rank_kernel<<<NQ, NQ>>>(labels, out);
}

// round 12
// speedup vs baseline: 1.6975x; 1.1393x over previous
#include <cuda_runtime.h>
#include <math.h>

// Problem constants (fixed: features [512,384] f32, labels [512] i32)
#define NQ 512
#define DIM 384
#define KSPLIT 6
#define KCH (DIM / KSPLIT)   // 64 per split
#define TS 64                // gram tile size (M and N)
#define KC 16                // gram k-chunk
#define SCALE 50.0f          // 1/(2*t2), t2 = 0.01  (tanh form of sigmoid)
#define KSEL 6.0f            // K = 5 + 1
#define SAT 5.0f             // truncation cut (validated R10: rel_err unchanged)
#define QMUL 2048.0f         // key quantizer: val*2048 < 2^23 for val < 4096

// Scratch (no allocations allowed anywhere)
__device__ float g_part[KSPLIT * NQ * NQ];  // partial Gram matrices (6 MB)
__device__ float g_sqp[KSPLIT * NQ];        // partial diagonal (squared norms)
__device__ float g_prec[NQ];                // per-query precision sums
__device__ unsigned int g_count = 0;        // ticket counter (reset after use)

__device__ __forceinline__ float fast_tanh(float x) {
    float r;
    asm("tanh.approx.f32 %0, %1;" : "=f"(r) : "f"(x));
    return r;
}

// ---------------------------------------------------------------------------
// Kernel 1: partial Gram. 64(M) x 64(N) tile, 4x4 microtile, K-split over z.
// Both smem tiles stored [k][row]: inner loop = 2x LDS.128 -> 16 FMA.
// (Distance-preservation validated R6/R7: identical loss under both grams.)
// ---------------------------------------------------------------------------
__global__ __launch_bounds__(256) void gram_kernel(const float* __restrict__ F) {
    __shared__ float As[KC][TS + 4];   // [k][m]
    __shared__ float Bs[KC][TS + 4];   // [k][n]

    const int bm = blockIdx.y * TS;
    const int bn = blockIdx.x * TS;
    const int kb = blockIdx.z * KCH;
    const int t  = threadIdx.x;
    const int tr = t >> 4;          // 0..15 -> 4 M-rows each
    const int tc = t & 15;          // 0..15 -> 4 N-cols each
    const int lr = t >> 2;          // 0..63 (load row)
    const int lc = (t & 3) * 4;     // 0,4,8,12 (load col group)

    float acc[4][4] = {};

    for (int k0 = kb; k0 < kb + KCH; k0 += KC) {
        {
            float4 av = *reinterpret_cast<const float4*>(&F[(bm + lr) * DIM + k0 + lc]);
            As[lc + 0][lr] = av.x;
            As[lc + 1][lr] = av.y;
            As[lc + 2][lr] = av.z;
            As[lc + 3][lr] = av.w;
            float4 bv = *reinterpret_cast<const float4*>(&F[(bn + lr) * DIM + k0 + lc]);
            Bs[lc + 0][lr] = bv.x;
            Bs[lc + 1][lr] = bv.y;
            Bs[lc + 2][lr] = bv.z;
            Bs[lc + 3][lr] = bv.w;
        }
        __syncthreads();

        #pragma unroll
        for (int kk = 0; kk < KC; kk++) {
            float4 a = *reinterpret_cast<const float4*>(&As[kk][4 * tr]);
            float4 b = *reinterpret_cast<const float4*>(&Bs[kk][4 * tc]);
            const float ar[4] = {a.x, a.y, a.z, a.w};
            const float br[4] = {b.x, b.y, b.z, b.w};
            #pragma unroll
            for (int i = 0; i < 4; i++)
                #pragma unroll
                for (int j = 0; j < 4; j++)
                    acc[i][j] = fmaf(ar[i], br[j], acc[i][j]);
        }
        __syncthreads();
    }

    float* dst = g_part + blockIdx.z * (NQ * NQ);
    #pragma unroll
    for (int i = 0; i < 4; i++) {
        #pragma unroll
        for (int j = 0; j < 4; j++) {
            const int r = bm + 4 * tr + i;
            const int c = bn + 4 * tc + j;
            dst[r * NQ + c] = acc[i][j];
            if (r == c) g_sqp[blockIdx.z * NQ + r] = acc[i][j];
        }
    }
}

// ---------------------------------------------------------------------------
// Kernel 2: rank + precision + fused final reduction.
// One block of 512 threads per query q.
//  - packed-key bitonic sort; cross-warp stages DOUBLE-BUFFERED: one barrier
//    per stage (write buf -> barrier -> read buf; next stage writes buf^1)
//  - sentinel-padded sorted array; window loop unrolled x4, SAT=5
//  - last-finishing block reduces g_prec -> scalar loss
// ---------------------------------------------------------------------------
__global__ __launch_bounds__(NQ) void rank_kernel(const int* __restrict__ labels,
                                                  float* __restrict__ out) {
    __shared__ float sq[NQ];          // summed squared norms
    __shared__ float va[NQ];          // exact value by ORIGINAL index
    __shared__ unsigned su[2][NQ];    // double-buffered sort scratch
    __shared__ float sve[3 * NQ];     // sentinel pad | sorted | sentinel pad
    __shared__ int   sl[NQ];          // labels staged in smem
    __shared__ float ws[16];
    __shared__ int isLast;

    const int q = blockIdx.x;
    const int p = threadIdx.x;

    // --- distance val0 = 50 * d(q, p); all reads coalesced ---
    {
        float s = 0.0f;
        #pragma unroll
        for (int z = 0; z < KSPLIT; z++) s += g_sqp[z * NQ + p];
        sq[p] = s;
    }
    sl[p] = labels[p];
    sve[p] = -1.0e9f;                 // left sentinel pad
    sve[2 * NQ + p] = 1.0e9f;         // right sentinel pad
    float gqp = 0.0f;
    {
        const int od = q * NQ + p;
        #pragma unroll
        for (int z = 0; z < KSPLIT; z++) gqp += g_part[z * NQ * NQ + od];
    }
    __syncthreads();
    const float val0 = SCALE * sqrtf(fmaxf(sq[q] + sq[p] - 2.0f * gqp, 0.0f));
    va[p] = val0;

    // --- packed key: quantized value (23b) | original index (9b) ---
    unsigned key = ((unsigned)(val0 * QMUL) << 9) | (unsigned)p;

    // --- bitonic sort of packed keys (ascending) ---
    int buf = 0;
    for (int k = 2; k <= NQ; k <<= 1) {
        const bool asc = ((p & k) == 0);
        for (int j = k >> 1; j >= 32; j >>= 1) {          // cross-warp, 1 barrier
            su[buf][p] = key;
            __syncthreads();
            unsigned ov = su[buf][p ^ j];
            buf ^= 1;                                     // next stage: other buffer
            const bool wantMin = (((p & j) == 0) == asc);
            key = wantMin ? umin(key, ov) : umax(key, ov);
        }
        const int j0 = ((k >> 1) < 32) ? (k >> 1) : 16;   // intra-warp via shfl
        for (int j = j0; j >= 1; j >>= 1) {
            unsigned ov = __shfl_xor_sync(0xffffffffu, key, j);
            const bool wantMin = (((p & j) == 0) == asc);
            key = wantMin ? umin(key, ov) : umax(key, ov);
        }
    }

    // --- recover exact value + original index at sorted slot p ---
    const int gidx = (int)(key & 511u);
    const float val = va[gidx];          // one scattered LDS per thread
    sve[NQ + p] = val;
    __syncthreads();

    // --- rank: exact position term + small tanh corrections ---
    const float* sc = sve + NQ + p;      // sc[-o] left, sc[o] right
    float corr = 0.0f;
    for (int o = 1; o < NQ; o += 4) {
        bool live = false;
        #pragma unroll
        for (int u = 0; u < 4; u++) {
            const float dvL = val - sc[-(o + u)];   // ~>= 0
            const float dvR = val - sc[o + u];      // ~<= 0
            const bool uL = dvL < SAT;
            const bool uR = dvR > -SAT;
            if (uL) corr += fast_tanh(dvL) - 1.0f;  // small
            if (uR) corr += fast_tanh(dvR) + 1.0f;  // small
            live |= (uL || uR);
        }
        if (!__any_sync(0xffffffffu, live)) break;
    }
    const float rank = 0.5f * (float)NQ
                     + 0.5f * ((float)(2 * p - (NQ - 1)) + corr);

    float contrib = 0.0f;
    if (sl[q] == sl[gidx]) {
        contrib = 1.0f / (1.0f + __expf(rank - KSEL));   // sigmoid(K - rank)
    }

    // --- per-block reduction (fixed tree, sorted order -> deterministic) ---
    #pragma unroll
    for (int o = 16; o; o >>= 1) contrib += __shfl_xor_sync(0xffffffffu, contrib, o);
    if ((p & 31) == 0) ws[p >> 5] = contrib;
    __syncthreads();
    if (p == 0) {
        float s = 0.0f;
        #pragma unroll
        for (int i = 0; i < 16; i++) s += ws[i];
        g_prec[q] = s;
        __threadfence();
        unsigned int t = atomicAdd(&g_count, 1u);
        isLast = (t == NQ - 1) ? 1 : 0;
    }
    __syncthreads();

    // --- last block: deterministic final reduction ---
    if (isLast) {
        __threadfence();
        float v = g_prec[p];
        #pragma unroll
        for (int o = 16; o; o >>= 1) v += __shfl_xor_sync(0xffffffffu, v, o);
        if ((p & 31) == 0) ws[p >> 5] = v;
        __syncthreads();
        if (p == 0) {
            float s = 0.0f;
            #pragma unroll
            for (int i = 0; i < 16; i++) s += ws[i];
            out[0] = 1.0f - s / (KSEL * (float)NQ);
            g_count = 0;   // reset for next graph replay
        }
    }
}

// ---------------------------------------------------------------------------
extern "C" void kernel_launch(void* const* d_in, const int* in_sizes, int n_in,
                              void* d_out, int out_size) {
    const float* F      = (const float*)d_in[0];
    const int*   labels = (const int*)d_in[1];
    float*       out    = (float*)d_out;

    gram_kernel<<<dim3(NQ / TS, NQ / TS, KSPLIT), 256>>>(F);
    rank_kernel<<<NQ, NQ>>>(labels, out);
}

// round 13
// speedup vs baseline: 1.9477x; 1.1474x over previous
#include <cuda_runtime.h>
#include <math.h>

// Problem constants (fixed: features [512,384] f32, labels [512] i32)
#define NQ 512
#define DIM 384
#define KSPLIT 6
#define KCH (DIM / KSPLIT)   // 64 per split
#define TS 64                // gram tile size (M and N)
#define KC 16                // gram k-chunk
#define SCALE 50.0f          // 1/(2*t2), t2 = 0.01  (tanh form of sigmoid)
#define KSEL 6.0f            // K = 5 + 1
#define SAT 5.0f             // truncation cut (validated R10: rel_err unchanged)
#define QMUL 2048.0f         // key quantizer: val*2048 < 2^23 for val < 4096
#define PMAX 64              // rank skip cutoff: rank > p/2 + 0.5 provably, so
                             // p >= 64 -> rank > 32.5 -> contrib < 3e-12 -> skip

// Scratch (no allocations allowed anywhere)
__device__ float g_part[KSPLIT * NQ * NQ];  // partial Gram matrices (6 MB)
__device__ float g_sqp[KSPLIT * NQ];        // partial diagonal (squared norms)
__device__ float g_prec[NQ];                // per-query precision sums
__device__ unsigned int g_count = 0;        // ticket counter (reset after use)

__device__ __forceinline__ float fast_tanh(float x) {
    float r;
    asm("tanh.approx.f32 %0, %1;" : "=f"(r) : "f"(x));
    return r;
}

// ---------------------------------------------------------------------------
// Kernel 1: partial Gram. 64(M) x 64(N) tile, 4x4 microtile, K-split over z.
// Both smem tiles stored [k][row]: inner loop = 2x LDS.128 -> 16 FMA.
// (UNCHANGED from R12 -- near its SIMT FFMA floor.)
// ---------------------------------------------------------------------------
__global__ __launch_bounds__(256) void gram_kernel(const float* __restrict__ F) {
    __shared__ float As[KC][TS + 4];   // [k][m]
    __shared__ float Bs[KC][TS + 4];   // [k][n]

    const int bm = blockIdx.y * TS;
    const int bn = blockIdx.x * TS;
    const int kb = blockIdx.z * KCH;
    const int t  = threadIdx.x;
    const int tr = t >> 4;          // 0..15 -> 4 M-rows each
    const int tc = t & 15;          // 0..15 -> 4 N-cols each
    const int lr = t >> 2;          // 0..63 (load row)
    const int lc = (t & 3) * 4;     // 0,4,8,12 (load col group)

    float acc[4][4] = {};

    for (int k0 = kb; k0 < kb + KCH; k0 += KC) {
        {
            float4 av = *reinterpret_cast<const float4*>(&F[(bm + lr) * DIM + k0 + lc]);
            As[lc + 0][lr] = av.x;
            As[lc + 1][lr] = av.y;
            As[lc + 2][lr] = av.z;
            As[lc + 3][lr] = av.w;
            float4 bv = *reinterpret_cast<const float4*>(&F[(bn + lr) * DIM + k0 + lc]);
            Bs[lc + 0][lr] = bv.x;
            Bs[lc + 1][lr] = bv.y;
            Bs[lc + 2][lr] = bv.z;
            Bs[lc + 3][lr] = bv.w;
        }
        __syncthreads();

        #pragma unroll
        for (int kk = 0; kk < KC; kk++) {
            float4 a = *reinterpret_cast<const float4*>(&As[kk][4 * tr]);
            float4 b = *reinterpret_cast<const float4*>(&Bs[kk][4 * tc]);
            const float ar[4] = {a.x, a.y, a.z, a.w};
            const float br[4] = {b.x, b.y, b.z, b.w};
            #pragma unroll
            for (int i = 0; i < 4; i++)
                #pragma unroll
                for (int j = 0; j < 4; j++)
                    acc[i][j] = fmaf(ar[i], br[j], acc[i][j]);
        }
        __syncthreads();
    }

    float* dst = g_part + blockIdx.z * (NQ * NQ);
    #pragma unroll
    for (int i = 0; i < 4; i++) {
        #pragma unroll
        for (int j = 0; j < 4; j++) {
            const int r = bm + 4 * tr + i;
            const int c = bn + 4 * tc + j;
            dst[r * NQ + c] = acc[i][j];
            if (r == c) g_sqp[blockIdx.z * NQ + r] = acc[i][j];
        }
    }
}

// ---------------------------------------------------------------------------
// Kernel 2: rank + precision + fused final reduction.
// One block of 512 threads per query q.
//  - packed-key bitonic sort (double-buffered cross-warp stages)
//  - RANK SKIP: rank > p/2 + 0.5 for any input (corr > -p), so only sorted
//    positions p < PMAX=64 can contribute; the window loop runs only in
//    warps 0-1, with tanh adds predicated on label match.
//  - last-finishing block reduces g_prec -> scalar loss
// ---------------------------------------------------------------------------
__global__ __launch_bounds__(NQ) void rank_kernel(const int* __restrict__ labels,
                                                  float* __restrict__ out) {
    __shared__ float sq[NQ];          // summed squared norms
    __shared__ float va[NQ];          // exact value by ORIGINAL index
    __shared__ unsigned su[2][NQ];    // double-buffered sort scratch
    __shared__ float sve[3 * NQ];     // sentinel pad | sorted | sentinel pad
    __shared__ int   sl[NQ];          // labels staged in smem
    __shared__ float ws[16];
    __shared__ int isLast;

    const int q = blockIdx.x;
    const int p = threadIdx.x;

    // --- distance val0 = 50 * d(q, p); all reads coalesced ---
    {
        float s = 0.0f;
        #pragma unroll
        for (int z = 0; z < KSPLIT; z++) s += g_sqp[z * NQ + p];
        sq[p] = s;
    }
    sl[p] = labels[p];
    sve[p] = -1.0e9f;                 // left sentinel pad
    sve[2 * NQ + p] = 1.0e9f;         // right sentinel pad
    float gqp = 0.0f;
    {
        const int od = q * NQ + p;
        #pragma unroll
        for (int z = 0; z < KSPLIT; z++) gqp += g_part[z * NQ * NQ + od];
    }
    __syncthreads();
    const float val0 = SCALE * sqrtf(fmaxf(sq[q] + sq[p] - 2.0f * gqp, 0.0f));
    va[p] = val0;

    // --- packed key: quantized value (23b) | original index (9b) ---
    unsigned key = ((unsigned)(val0 * QMUL) << 9) | (unsigned)p;

    // --- bitonic sort of packed keys (ascending) ---
    int buf = 0;
    for (int k = 2; k <= NQ; k <<= 1) {
        const bool asc = ((p & k) == 0);
        for (int j = k >> 1; j >= 32; j >>= 1) {          // cross-warp, 1 barrier
            su[buf][p] = key;
            __syncthreads();
            unsigned ov = su[buf][p ^ j];
            buf ^= 1;                                     // next stage: other buffer
            const bool wantMin = (((p & j) == 0) == asc);
            key = wantMin ? umin(key, ov) : umax(key, ov);
        }
        const int j0 = ((k >> 1) < 32) ? (k >> 1) : 16;   // intra-warp via shfl
        for (int j = j0; j >= 1; j >>= 1) {
            unsigned ov = __shfl_xor_sync(0xffffffffu, key, j);
            const bool wantMin = (((p & j) == 0) == asc);
            key = wantMin ? umin(key, ov) : umax(key, ov);
        }
    }

    // --- recover exact value + original index at sorted slot p ---
    const int gidx = (int)(key & 511u);
    const float val = va[gidx];          // one scattered LDS per thread
    sve[NQ + p] = val;
    __syncthreads();

    // --- rank + contrib, ONLY where it can matter (p < PMAX, label match) ---
    float contrib = 0.0f;
    if (p < PMAX) {                      // warp-uniform: warps 0,1 only
        const bool need = (sl[q] == sl[gidx]);
        const float* sc = sve + NQ + p;  // sc[-o] left, sc[o] right
        float corr = 0.0f;
        for (int o = 1; o < NQ; o += 4) {
            bool live = false;
            #pragma unroll
            for (int u = 0; u < 4; u++) {
                const float dvL = val - sc[-(o + u)];   // ~>= 0, grows with o
                const float dvR = val - sc[o + u];      // ~<= 0, falls with o
                const bool uL = dvL < SAT;
                const bool uR = dvR > -SAT;
                if (need && uL) corr += fast_tanh(dvL) - 1.0f;  // small
                if (need && uR) corr += fast_tanh(dvR) + 1.0f;  // small
                live |= (need && (uL || uR));
            }
            if (!__any_sync(0xffffffffu, live)) break;
        }
        if (need) {
            const float rank = 0.5f * (float)NQ
                             + 0.5f * ((float)(2 * p - (NQ - 1)) + corr);
            contrib = 1.0f / (1.0f + __expf(rank - KSEL));  // sigmoid(K - rank)
        }
    }

    // --- per-block reduction (fixed tree, sorted order -> deterministic) ---
    #pragma unroll
    for (int o = 16; o; o >>= 1) contrib += __shfl_xor_sync(0xffffffffu, contrib, o);
    if ((p & 31) == 0) ws[p >> 5] = contrib;
    __syncthreads();
    if (p == 0) {
        float s = 0.0f;
        #pragma unroll
        for (int i = 0; i < 16; i++) s += ws[i];
        g_prec[q] = s;
        __threadfence();
        unsigned int t = atomicAdd(&g_count, 1u);
        isLast = (t == NQ - 1) ? 1 : 0;
    }
    __syncthreads();

    // --- last block: deterministic final reduction ---
    if (isLast) {
        __threadfence();
        float v = g_prec[p];
        #pragma unroll
        for (int o = 16; o; o >>= 1) v += __shfl_xor_sync(0xffffffffu, v, o);
        if ((p & 31) == 0) ws[p >> 5] = v;
        __syncthreads();
        if (p == 0) {
            float s = 0.0f;
            #pragma unroll
            for (int i = 0; i < 16; i++) s += ws[i];
            out[0] = 1.0f - s / (KSEL * (float)NQ);
            g_count = 0;   // reset for next graph replay
        }
    }
}

// ---------------------------------------------------------------------------
extern "C" void kernel_launch(void* const* d_in, const int* in_sizes, int n_in,
                              void* d_out, int out_size) {
    const float* F      = (const float*)d_in[0];
    const int*   labels = (const int*)d_in[1];
    float*       out    = (float*)d_out;

    gram_kernel<<<dim3(NQ / TS, NQ / TS, KSPLIT), 256>>>(F);
    rank_kernel<<<NQ, NQ>>>(labels, out);
}

// round 14
// speedup vs baseline: 2.0057x; 1.0298x over previous
#include <cuda_runtime.h>
#include <math.h>

// Problem constants (fixed: features [512,384] f32, labels [512] i32)
#define NQ 512
#define DIM 384
#define KSPLIT 6
#define KCH (DIM / KSPLIT)   // 64 per split
#define TS 64                // gram tile size (M and N)
#define KC 16                // gram k-chunk
#define SCALE 50.0f          // 1/(2*t2): sigmoid(z)=0.5+0.5*tanh(z/2), z/2=50*d_diff
#define KSEL 6.0f            // K = 5 + 1

// Scratch (no allocations allowed anywhere)
__device__ float g_part[KSPLIT * NQ * NQ];  // partial Gram matrices (6 MB)
__device__ float g_sqp[KSPLIT * NQ];        // partial diagonal (squared norms)
__device__ float g_prec[NQ];                // per-query precision sums
__device__ unsigned int g_count = 0;        // ticket counter (reset after use)

__device__ __forceinline__ float fast_tanh(float x) {
    float r;
    asm("tanh.approx.f32 %0, %1;" : "=f"(r) : "f"(x));
    return r;
}

// ---------------------------------------------------------------------------
// Kernel 1: partial Gram. 64(M) x 64(N) tile, 4x4 microtile, K-split over z.
// (UNCHANGED from R12/R13 -- near its SIMT FFMA floor.)
// ---------------------------------------------------------------------------
__global__ __launch_bounds__(256) void gram_kernel(const float* __restrict__ F) {
    __shared__ float As[KC][TS + 4];   // [k][m]
    __shared__ float Bs[KC][TS + 4];   // [k][n]

    const int bm = blockIdx.y * TS;
    const int bn = blockIdx.x * TS;
    const int kb = blockIdx.z * KCH;
    const int t  = threadIdx.x;
    const int tr = t >> 4;
    const int tc = t & 15;
    const int lr = t >> 2;
    const int lc = (t & 3) * 4;

    float acc[4][4] = {};

    for (int k0 = kb; k0 < kb + KCH; k0 += KC) {
        {
            float4 av = *reinterpret_cast<const float4*>(&F[(bm + lr) * DIM + k0 + lc]);
            As[lc + 0][lr] = av.x;
            As[lc + 1][lr] = av.y;
            As[lc + 2][lr] = av.z;
            As[lc + 3][lr] = av.w;
            float4 bv = *reinterpret_cast<const float4*>(&F[(bn + lr) * DIM + k0 + lc]);
            Bs[lc + 0][lr] = bv.x;
            Bs[lc + 1][lr] = bv.y;
            Bs[lc + 2][lr] = bv.z;
            Bs[lc + 3][lr] = bv.w;
        }
        __syncthreads();

        #pragma unroll
        for (int kk = 0; kk < KC; kk++) {
            float4 a = *reinterpret_cast<const float4*>(&As[kk][4 * tr]);
            float4 b = *reinterpret_cast<const float4*>(&Bs[kk][4 * tc]);
            const float ar[4] = {a.x, a.y, a.z, a.w};
            const float br[4] = {b.x, b.y, b.z, b.w};
            #pragma unroll
            for (int i = 0; i < 4; i++)
                #pragma unroll
                for (int j = 0; j < 4; j++)
                    acc[i][j] = fmaf(ar[i], br[j], acc[i][j]);
        }
        __syncthreads();
    }

    float* dst = g_part + blockIdx.z * (NQ * NQ);
    #pragma unroll
    for (int i = 0; i < 4; i++) {
        #pragma unroll
        for (int j = 0; j < 4; j++) {
            const int r = bm + 4 * tr + i;
            const int c = bn + 4 * tc + j;
            dst[r * NQ + c] = acc[i][j];
            if (r == c) g_sqp[blockIdx.z * NQ + r] = acc[i][j];
        }
    }
}

// ---------------------------------------------------------------------------
// Kernel 2: rank + precision + fused final reduction. NO SORT.
// One block of 512 threads per query q.
//  - val[p] = 50 * d(q,p) -> smem (coalesced partial sums)
//  - matched list (labels[g]==labels[q], ~8 items) built deterministically
//    via ballot + cross-warp prefix
//  - warp w computes rank of matched item m=w directly:
//      rank_m = 256 + 0.5 * sum_p tanh(val_m - val_p)
//    (tanh.approx saturates exactly -> no pruning needed; 512 terms/warp,
//     16 lane-strided each, fixed-tree reduce -> deterministic)
//  - contrib_m = sigmoid(K - rank_m); block-reduce; last block -> loss
// ---------------------------------------------------------------------------
__global__ __launch_bounds__(NQ) void rank_kernel(const int* __restrict__ labels,
                                                  float* __restrict__ out) {
    __shared__ float sq[NQ];      // summed squared norms
    __shared__ float va[NQ];      // val by gallery index
    __shared__ int   sl[NQ];      // labels staged in smem
    __shared__ int   mlist[NQ];   // matched gallery indices (worst case NQ)
    __shared__ float cm[NQ];      // contrib per matched item
    __shared__ int   wcount[16];  // per-warp match counts
    __shared__ float ws[16];
    __shared__ int isLast;

    const int q = blockIdx.x;
    const int p = threadIdx.x;
    const int wid = p >> 5;
    const int lid = p & 31;

    // --- distance val = 50 * d(q, p); all reads coalesced ---
    {
        float s = 0.0f;
        #pragma unroll
        for (int z = 0; z < KSPLIT; z++) s += g_sqp[z * NQ + p];
        sq[p] = s;
    }
    sl[p] = labels[p];
    cm[p] = 0.0f;
    float gqp = 0.0f;
    {
        const int od = q * NQ + p;
        #pragma unroll
        for (int z = 0; z < KSPLIT; z++) gqp += g_part[z * NQ * NQ + od];
    }
    __syncthreads();
    const float val = SCALE * sqrtf(fmaxf(sq[q] + sq[p] - 2.0f * gqp, 0.0f));
    va[p] = val;

    // --- deterministic matched-list build (index order preserved) ---
    const bool mflag = (sl[p] == sl[q]);
    const unsigned ballot = __ballot_sync(0xffffffffu, mflag);
    if (lid == 0) wcount[wid] = __popc(ballot);
    __syncthreads();
    int base = 0, M = 0;
    #pragma unroll
    for (int w = 0; w < 16; w++) {
        const int c = wcount[w];
        base += (w < wid) ? c : 0;
        M += c;
    }
    if (mflag) mlist[base + __popc(ballot & ((1u << lid) - 1u))] = p;
    __syncthreads();

    // --- per-warp direct rank of matched items (warp w -> item m=w, strided) ---
    for (int m = wid; m < M; m += 16) {
        const float vm = va[mlist[m]];          // broadcast LDS
        float acc = 0.0f;
        #pragma unroll
        for (int i = 0; i < 16; i++) {
            acc += fast_tanh(vm - va[lid + 32 * i]);
        }
        #pragma unroll
        for (int o = 16; o; o >>= 1) acc += __shfl_xor_sync(0xffffffffu, acc, o);
        if (lid == 0) {
            const float rank = 0.5f * (float)NQ + 0.5f * acc;
            cm[m] = 1.0f / (1.0f + __expf(rank - KSEL));   // sigmoid(K - rank)
        }
    }
    __syncthreads();

    // --- block reduction of matched contribs (fixed tree, deterministic) ---
    float contrib = cm[p];                       // zero beyond M
    #pragma unroll
    for (int o = 16; o; o >>= 1) contrib += __shfl_xor_sync(0xffffffffu, contrib, o);
    if (lid == 0) ws[wid] = contrib;
    __syncthreads();
    if (p == 0) {
        float s = 0.0f;
        #pragma unroll
        for (int i = 0; i < 16; i++) s += ws[i];
        g_prec[q] = s;
        __threadfence();
        unsigned int t = atomicAdd(&g_count, 1u);
        isLast = (t == NQ - 1) ? 1 : 0;
    }
    __syncthreads();

    // --- last block: deterministic final reduction -> scalar loss ---
    if (isLast) {
        __threadfence();
        float v = g_prec[p];
        #pragma unroll
        for (int o = 16; o; o >>= 1) v += __shfl_xor_sync(0xffffffffu, v, o);
        if (lid == 0) ws[wid] = v;
        __syncthreads();
        if (p == 0) {
            float s = 0.0f;
            #pragma unroll
            for (int i = 0; i < 16; i++) s += ws[i];
            out[0] = 1.0f - s / (KSEL * (float)NQ);
            g_count = 0;   // reset for next graph replay
        }
    }
}

// ---------------------------------------------------------------------------
extern "C" void kernel_launch(void* const* d_in, const int* in_sizes, int n_in,
                              void* d_out, int out_size) {
    const float* F      = (const float*)d_in[0];
    const int*   labels = (const int*)d_in[1];
    float*       out    = (float*)d_out;

    gram_kernel<<<dim3(NQ / TS, NQ / TS, KSPLIT), 256>>>(F);
    rank_kernel<<<NQ, NQ>>>(labels, out);
}